// round 1
// baseline (speedup 1.0000x reference)
#include <cuda_runtime.h>
#include <cstddef>

#define BB 512
#define TT 200
#define SI 100
#define DI 68
#define HS 256
#define HD 128
#define NN 10000
#define DDIM 512   // 2*HD + HS

// ---------------- scratch (static device arrays; no runtime allocation) ----------------
__device__ float g_s[BB * HS];                 // static branch output [B,HS]
__device__ float g_d[BB * TT * HD];            // relu(dyn proj) [B,T,HD]
__device__ float g_xwf[BB * TT * HD];          // xw fwd, overwritten by fwd hidden states
__device__ float g_xwb[BB * TT * HD];          // xw bwd, overwritten by bwd hidden states
__device__ float g_cs[BB];                     // per-trial static dot + bias
__device__ float g_wdyn_t[DI * HD];            // w_dyn transposed [DI][HD]
__device__ float g_wihf_t[HD * HD];            // w_ih_f transposed [k][o]
__device__ float g_wihb_t[HD * HD];
__device__ float g_whhf_t[HD * HD];            // w_hh_f transposed [k][o]
__device__ float g_whhb_t[HD * HD];
__device__ float g_bxf[HD];                    // b_ih_f + b_hh_f
__device__ float g_bxb[HD];

// ---------------- prep: transposes + bias folds ----------------
__global__ void prep_kernel(const float* __restrict__ w_dyn,
                            const float* __restrict__ w_ih_f,
                            const float* __restrict__ w_hh_f,
                            const float* __restrict__ w_ih_b,
                            const float* __restrict__ w_hh_b,
                            const float* __restrict__ b_ih_f,
                            const float* __restrict__ b_hh_f,
                            const float* __restrict__ b_ih_b,
                            const float* __restrict__ b_hh_b) {
    int idx = blockIdx.x * blockDim.x + threadIdx.x;
    if (idx < HD * HD) {
        int o = idx / HD, k = idx % HD;
        g_wihf_t[k * HD + o] = w_ih_f[idx];
        g_wihb_t[k * HD + o] = w_ih_b[idx];
        g_whhf_t[k * HD + o] = w_hh_f[idx];
        g_whhb_t[k * HD + o] = w_hh_b[idx];
    }
    if (idx < HD * DI) {               // w_dyn is [HD,DI] row-major
        int o = idx / DI, i = idx % DI;
        g_wdyn_t[i * HD + o] = w_dyn[idx];
    }
    if (idx < HD) {
        g_bxf[idx] = b_ih_f[idx] + b_hh_f[idx];
        g_bxb[idx] = b_ih_b[idx] + b_hh_b[idx];
    }
}

// ---------------- static branch: 2-layer MLP, one block per trial ----------------
__global__ void static_kernel(const float* __restrict__ xs,
                              const float* __restrict__ w1, const float* __restrict__ b1,
                              const float* __restrict__ w2, const float* __restrict__ b2) {
    int b = blockIdx.x;
    int j = threadIdx.x;                // 256 threads, one per hidden unit
    __shared__ float xsh[SI];
    __shared__ float s1[HS];
    if (j < SI) xsh[j] = xs[b * SI + j];
    __syncthreads();
    float acc = b1[j];
    #pragma unroll 4
    for (int i = 0; i < SI; i++) acc += xsh[i] * w1[j * SI + i];
    s1[j] = fmaxf(acc, 0.f);
    __syncthreads();
    acc = b2[j];
    #pragma unroll 4
    for (int i = 0; i < HS; i++) acc += s1[i] * w2[j * HS + i];
    g_s[b * HS + j] = fmaxf(acc, 0.f);
}

// ---------------- dynamic input projection: d = relu(x_dyn @ w_dyn^T + b) ----------------
// 8 rows per block, 128 threads = one output column each.
__global__ void dynproj_kernel(const float* __restrict__ xd,
                               const float* __restrict__ bdyn) {
    __shared__ float a[8][DI];
    int row0 = blockIdx.x * 8;
    int tid = threadIdx.x;
    const float* src = xd + (size_t)row0 * DI;
    for (int i = tid; i < 8 * DI; i += 128) ((float*)a)[i] = src[i];
    __syncthreads();

    int o = tid;
    float bo = bdyn[o];
    float acc[8];
    #pragma unroll
    for (int r = 0; r < 8; r++) acc[r] = bo;

    #pragma unroll 4
    for (int k = 0; k < DI; k += 4) {
        float w0 = g_wdyn_t[(k + 0) * HD + o];
        float w1 = g_wdyn_t[(k + 1) * HD + o];
        float w2 = g_wdyn_t[(k + 2) * HD + o];
        float w3 = g_wdyn_t[(k + 3) * HD + o];
        #pragma unroll
        for (int r = 0; r < 8; r++) {
            float4 h = *(const float4*)&a[r][k];
            acc[r] += h.x * w0 + h.y * w1 + h.z * w2 + h.w * w3;
        }
    }
    #pragma unroll
    for (int r = 0; r < 8; r++)
        g_d[(size_t)(row0 + r) * HD + o] = fmaxf(acc[r], 0.f);
}

// ---------------- dual GEMM: xw_f / xw_b = d @ w_ih^T + (b_ih + b_hh) ----------------
__global__ void xwgemm_kernel() {
    __shared__ float a[8][HD];
    int row0 = blockIdx.x * 8;
    int tid = threadIdx.x;
    const float4* src = (const float4*)(g_d + (size_t)row0 * HD);
    float4* dst = (float4*)a;
    for (int i = tid; i < 8 * HD / 4; i += 128) dst[i] = src[i];
    __syncthreads();

    int o = tid;
    float accf[8], accb[8];
    float bf = g_bxf[o], bbv = g_bxb[o];
    #pragma unroll
    for (int r = 0; r < 8; r++) { accf[r] = bf; accb[r] = bbv; }

    #pragma unroll 2
    for (int k = 0; k < HD; k += 4) {
        float wf0 = g_wihf_t[(k + 0) * HD + o];
        float wf1 = g_wihf_t[(k + 1) * HD + o];
        float wf2 = g_wihf_t[(k + 2) * HD + o];
        float wf3 = g_wihf_t[(k + 3) * HD + o];
        float wb0 = g_wihb_t[(k + 0) * HD + o];
        float wb1 = g_wihb_t[(k + 1) * HD + o];
        float wb2 = g_wihb_t[(k + 2) * HD + o];
        float wb3 = g_wihb_t[(k + 3) * HD + o];
        #pragma unroll
        for (int r = 0; r < 8; r++) {
            float4 h = *(const float4*)&a[r][k];
            accf[r] += h.x * wf0 + h.y * wf1 + h.z * wf2 + h.w * wf3;
            accb[r] += h.x * wb0 + h.y * wb1 + h.z * wb2 + h.w * wb3;
        }
    }
    #pragma unroll
    for (int r = 0; r < 8; r++) {
        size_t idx = (size_t)(row0 + r) * HD + o;
        g_xwf[idx] = accf[r];
        g_xwb[idx] = accb[r];
    }
}

// ---------------- RNN scan: h = relu(xw_t + h @ Whh^T), both directions ----------------
// grid = 128 blocks: even = fwd chunk, odd = bwd chunk; 8 trials per block.
// 256 threads: o = tid&127, each half-block handles 4 trials.
// Whh read from global (stays hot in L1: 64KB per direction).
__global__ void rnn_scan_kernel() {
    int dir = blockIdx.x & 1;
    int b0 = (blockIdx.x >> 1) * 8;
    const float* __restrict__ W = dir ? g_whhb_t : g_whhf_t;
    float* __restrict__ xw = dir ? g_xwb : g_xwf;

    __shared__ float h_sh[8][HD];
    int o = threadIdx.x & 127;
    int r0 = (threadIdx.x >> 7) * 4;

    #pragma unroll
    for (int r = 0; r < 4; r++) h_sh[r0 + r][o] = 0.f;
    __syncthreads();

    for (int step = 0; step < TT; ++step) {
        int t = dir ? (TT - 1 - step) : step;
        size_t base = ((size_t)(b0 + r0) * TT + t) * HD + o;
        float acc[4];
        #pragma unroll
        for (int r = 0; r < 4; r++) acc[r] = xw[base + (size_t)r * TT * HD];

        #pragma unroll 8
        for (int k = 0; k < HD; k += 4) {
            float w0 = W[(k + 0) * HD + o];
            float w1 = W[(k + 1) * HD + o];
            float w2 = W[(k + 2) * HD + o];
            float w3 = W[(k + 3) * HD + o];
            #pragma unroll
            for (int r = 0; r < 4; r++) {
                float4 h = *(const float4*)&h_sh[r0 + r][k];
                acc[r] += h.x * w0 + h.y * w1 + h.z * w2 + h.w * w3;
            }
        }
        __syncthreads();   // all reads of old h done
        #pragma unroll
        for (int r = 0; r < 4; r++) {
            float v = fmaxf(acc[r], 0.f);
            h_sh[r0 + r][o] = v;
            xw[base + (size_t)r * TT * HD] = v;   // in-place: becomes the RNN output
        }
        __syncthreads();   // new h visible before next step
    }
}

// ---------------- c_s[b] = <s[b], Wn[:256]> + bn ----------------
__global__ void cs_kernel(const int* __restrict__ order,
                          const float* __restrict__ nw,
                          const float* __restrict__ nb) {
    int b = blockIdx.x;
    int tid = threadIdx.x;               // 256
    int n = order[b];
    float v = g_s[b * HS + tid] * nw[(size_t)n * DDIM + tid];
    #pragma unroll
    for (int s = 16; s > 0; s >>= 1) v += __shfl_down_sync(0xffffffffu, v, s);
    __shared__ float partial[8];
    if ((tid & 31) == 0) partial[tid >> 5] = v;
    __syncthreads();
    if (tid == 0) {
        float sum = 0.f;
        #pragma unroll
        for (int i = 0; i < 8; i++) sum += partial[i];
        g_cs[b] = sum + nb[n];
    }
}

// ---------------- out[b,t] = relu(c_s[b] + <fwd, Wn[256:384]> + <bwd, Wn[384:512]>) ----------------
__global__ void out_kernel(const int* __restrict__ order,
                           const float* __restrict__ nw,
                           float* __restrict__ out) {
    int b = blockIdx.x;
    int tid = threadIdx.x;               // 256 = 8 warps
    int n = order[b];
    __shared__ float wsh[2 * HD];
    wsh[tid] = nw[(size_t)n * DDIM + HS + tid];
    __syncthreads();
    float cs = g_cs[b];
    int w = tid >> 5, l = tid & 31;
    for (int i = 0; i < 25; i++) {
        int t = w + 8 * i;
        size_t base = ((size_t)b * TT + t) * HD;
        float acc = 0.f;
        #pragma unroll
        for (int c = 0; c < 4; c++) {
            acc += g_xwf[base + c * 32 + l] * wsh[c * 32 + l];
            acc += g_xwb[base + c * 32 + l] * wsh[HD + c * 32 + l];
        }
        #pragma unroll
        for (int s = 16; s > 0; s >>= 1) acc += __shfl_down_sync(0xffffffffu, acc, s);
        if (l == 0) out[b * TT + t] = fmaxf(acc + cs, 0.f);
    }
}

// ---------------- launch ----------------
extern "C" void kernel_launch(void* const* d_in, const int* in_sizes, int n_in,
                              void* d_out, int out_size) {
    const float* x_static  = (const float*)d_in[0];
    const float* x_dynamic = (const float*)d_in[1];
    const int*   order     = (const int*)  d_in[2];
    const float* w_s1      = (const float*)d_in[3];
    const float* b_s1      = (const float*)d_in[4];
    const float* w_s2      = (const float*)d_in[5];
    const float* b_s2      = (const float*)d_in[6];
    const float* w_dyn     = (const float*)d_in[7];
    const float* b_dyn     = (const float*)d_in[8];
    const float* w_ih_f    = (const float*)d_in[9];
    const float* w_hh_f    = (const float*)d_in[10];
    const float* b_ih_f    = (const float*)d_in[11];
    const float* b_hh_f    = (const float*)d_in[12];
    const float* w_ih_b    = (const float*)d_in[13];
    const float* w_hh_b    = (const float*)d_in[14];
    const float* b_ih_b    = (const float*)d_in[15];
    const float* b_hh_b    = (const float*)d_in[16];
    const float* nw        = (const float*)d_in[17];
    const float* nb        = (const float*)d_in[18];
    float* out = (float*)d_out;

    prep_kernel<<<64, 256>>>(w_dyn, w_ih_f, w_hh_f, w_ih_b, w_hh_b,
                             b_ih_f, b_hh_f, b_ih_b, b_hh_b);
    static_kernel<<<BB, 256>>>(x_static, w_s1, b_s1, w_s2, b_s2);
    dynproj_kernel<<<BB * TT / 8, 128>>>(x_dynamic, b_dyn);
    xwgemm_kernel<<<BB * TT / 8, 128>>>();
    rnn_scan_kernel<<<128, 256>>>();
    cs_kernel<<<BB, 256>>>(order, nw, nb);
    out_kernel<<<BB, 256>>>(order, nw, out);
}